// round 8
// baseline (speedup 1.0000x reference)
#include <cuda_runtime.h>
#include <cuda_bf16.h>

#define NN   100000
#define NPAD 100096            // 782 * 128
#define EMAX 1600000
#define SROW 24                // smem row stride (bf16 elems); 48B -> conflict-free ldmatrix

// ---------------- scratch (device globals; no allocation allowed) ----------
__device__ __nv_bfloat16 g_ahi[(size_t)NPAD * 128];
__device__ __nv_bfloat16 g_alo[(size_t)NPAD * 128];
__device__ float         g_ys[(size_t)NPAD * 128];
__device__ float         g_yn[(size_t)NPAD * 128];
__device__ __nv_bfloat16 g_bthi[256 * 128];           // packed B^T hi  [2N][K]
__device__ __nv_bfloat16 g_btlo[256 * 128];           // packed B^T lo
__device__ int g_deg[NN];
__device__ int g_off[NN + 1];
__device__ int g_cur[NN];
__device__ int g_csr[EMAX];

// ---------------- CSR build -------------------------------------------------
__global__ void k_zero_deg() {
    for (int i = blockIdx.x * blockDim.x + threadIdx.x; i < NN;
         i += gridDim.x * blockDim.x)
        g_deg[i] = 0;
}

__global__ void k_count(const int* __restrict__ dst, int E) {
    int i0 = (blockIdx.x * blockDim.x + threadIdx.x) * 4;
    if (i0 + 3 < E) {
        int4 d = *(const int4*)(dst + i0);
        atomicAdd(&g_deg[d.x], 1);
        atomicAdd(&g_deg[d.y], 1);
        atomicAdd(&g_deg[d.z], 1);
        atomicAdd(&g_deg[d.w], 1);
    } else {
        for (int j = 0; j < 4; j++) {
            int i = i0 + j;
            if (i < E) atomicAdd(&g_deg[dst[i]], 1);
        }
    }
}

__global__ void k_scan() {
    __shared__ int ss[1024];
    int t = threadIdx.x;
    const int CH = (NN + 1023) / 1024;
    int beg = t * CH; if (beg > NN) beg = NN;
    int end = beg + CH; if (end > NN) end = NN;
    int s = 0;
    for (int i = beg; i < end; i++) s += g_deg[i];
    ss[t] = s;
    __syncthreads();
    for (int d = 1; d < 1024; d <<= 1) {
        int v = (t >= d) ? ss[t - d] : 0;
        __syncthreads();
        ss[t] += v;
        __syncthreads();
    }
    int run = ss[t] - s;
    for (int i = beg; i < end; i++) {
        g_off[i] = run;
        g_cur[i] = run;
        run += g_deg[i];
    }
    if (t == 1023) g_off[NN] = ss[1023];
}

__global__ void k_scatter(const int* __restrict__ src, const int* __restrict__ dst, int E) {
    int i0 = (blockIdx.x * blockDim.x + threadIdx.x) * 4;
    if (i0 + 3 < E) {
        int4 d = *(const int4*)(dst + i0);
        int4 s = *(const int4*)(src + i0);
        int p0 = atomicAdd(&g_cur[d.x], 1);
        int p1 = atomicAdd(&g_cur[d.y], 1);
        int p2 = atomicAdd(&g_cur[d.z], 1);
        int p3 = atomicAdd(&g_cur[d.w], 1);
        g_csr[p0] = s.x; g_csr[p1] = s.y; g_csr[p2] = s.z; g_csr[p3] = s.w;
    } else {
        for (int j = 0; j < 4; j++) {
            int i = i0 + j;
            if (i < E) {
                int p = atomicAdd(&g_cur[dst[i]], 1);
                g_csr[p] = src[i];
            }
        }
    }
}

// ---------------- weight pack: [Ws | Wn] -> B^T bf16 hi/lo -----------------
__global__ void k_pack(const float* __restrict__ ws, const float* __restrict__ wn,
                       int K, int N)
{
    int idx = blockIdx.x * blockDim.x + threadIdx.x;
    int total = 2 * N * K;
    if (idx >= total) return;
    int n = idx / K, k = idx - n * K;
    float v = (n < N) ? ws[k * N + n] : wn[k * N + (n - N)];
    __nv_bfloat16 h = __float2bfloat16(v);
    g_bthi[n * K + k] = h;
    g_btlo[n * K + k] = __float2bfloat16(v - __bfloat162float(h));
}

// ---------------- fp32 -> bf16 hi/lo split of the input features -----------
__global__ void k_split4(const float* __restrict__ x, int n4) {
    int i = blockIdx.x * blockDim.x + threadIdx.x;
    if (i >= n4) return;
    float4 v = ((const float4*)x)[i];
    __nv_bfloat16 hx = __float2bfloat16(v.x), hy = __float2bfloat16(v.y);
    __nv_bfloat16 hz = __float2bfloat16(v.z), hw = __float2bfloat16(v.w);
    __nv_bfloat162 h01, h23, l01, l23;
    h01.x = hx; h01.y = hy; h23.x = hz; h23.y = hw;
    l01.x = __float2bfloat16(v.x - __bfloat162float(hx));
    l01.y = __float2bfloat16(v.y - __bfloat162float(hy));
    l23.x = __float2bfloat16(v.z - __bfloat162float(hz));
    l23.y = __float2bfloat16(v.w - __bfloat162float(hw));
    uint2 hp, lp;
    hp.x = *(unsigned*)&h01; hp.y = *(unsigned*)&h23;
    lp.x = *(unsigned*)&l01; lp.y = *(unsigned*)&l23;
    ((uint2*)g_ahi)[i] = hp;
    ((uint2*)g_alo)[i] = lp;
}

// ---------------- tensor-core GEMM (split bf16, 3 products, pipelined) ------
#define MMA16816(d, a0, a1, a2, a3, b0, b1)                                    \
    asm volatile(                                                              \
        "mma.sync.aligned.m16n8k16.row.col.f32.bf16.bf16.f32 "                 \
        "{%0,%1,%2,%3}, {%4,%5,%6,%7}, {%8,%9}, {%0,%1,%2,%3};"               \
        : "+f"(d[0]), "+f"(d[1]), "+f"(d[2]), "+f"(d[3])                       \
        : "r"(a0), "r"(a1), "r"(a2), "r"(a3), "r"(b0), "r"(b1))

__device__ __forceinline__ void ldsm4(unsigned& r0, unsigned& r1,
                                      unsigned& r2, unsigned& r3, unsigned addr) {
    asm volatile("ldmatrix.sync.aligned.m8n8.x4.shared.b16 {%0,%1,%2,%3}, [%4];"
                 : "=r"(r0), "=r"(r1), "=r"(r2), "=r"(r3) : "r"(addr));
}

__device__ __forceinline__ void cpasync16(unsigned dst, const void* src) {
    asm volatile("cp.async.ca.shared.global [%0], [%1], 16;" :: "r"(dst), "l"(src));
}

// C = A[M,K] * Bt[2Nself,K]^T, split into Cs (cols < Nself) and Cn, both [M][Nself].
// Block tile 128x128, 8 warps (4m x 2n), warp tile 32x64.
// 2-stage cp.async double buffer, ldmatrix fragment loads. (Proven R5 design.)
__global__ __launch_bounds__(256, 2)
void k_gemm_mma(const __nv_bfloat16* __restrict__ Ahi,
                const __nv_bfloat16* __restrict__ Alo,
                float* __restrict__ Cs, float* __restrict__ Cn,
                int K, int Nself)
{
    __shared__ __align__(16) __nv_bfloat16 sm[2 * 4 * 128 * SROW];
    const int TILE = 128 * SROW;                // elems per tile

    const int tid = threadIdx.x;
    const int warp = tid >> 5, lane = tid & 31;
    const int wm = warp & 3, wn = warp >> 2;
    const size_t rowbase = (size_t)blockIdx.x * 128;
    const int    colbase = blockIdx.y * 128;

    const int lr = tid >> 1;
    const int lc = (tid & 1) * 8;

    const unsigned sbase = (unsigned)__cvta_generic_to_shared(sm);
    const unsigned sdst = sbase + (unsigned)(lr * SROW + lc) * 2;

    const __nv_bfloat16* gsrc0 = Ahi    + (rowbase + lr) * K + lc;
    const __nv_bfloat16* gsrc1 = Alo    + (rowbase + lr) * K + lc;
    const __nv_bfloat16* gsrc2 = g_bthi + (size_t)(colbase + lr) * K + lc;
    const __nv_bfloat16* gsrc3 = g_btlo + (size_t)(colbase + lr) * K + lc;

    float acc[2][8][4];
#pragma unroll
    for (int i = 0; i < 2; i++)
#pragma unroll
        for (int j = 0; j < 8; j++)
#pragma unroll
            for (int q = 0; q < 4; q++) acc[i][j][q] = 0.f;

    const int KT = K >> 4;

    cpasync16(sdst + 0 * TILE * 2, gsrc0);
    cpasync16(sdst + 1 * TILE * 2, gsrc1);
    cpasync16(sdst + 2 * TILE * 2, gsrc2);
    cpasync16(sdst + 3 * TILE * 2, gsrc3);
    asm volatile("cp.async.commit_group;");

    const int a_row = (lane & 15);
    const int a_kh  = (lane >> 4) * 8;
    const int b_n   = (lane & 7) + (lane >> 4) * 8;
    const int b_kh  = ((lane >> 3) & 1) * 8;

    for (int it = 0; it < KT; it++) {
        if (it + 1 < KT) {
            unsigned d = sdst + (unsigned)(((it + 1) & 1) * 4) * TILE * 2;
            int ko = (it + 1) * 16;
            cpasync16(d + 0 * TILE * 2, gsrc0 + ko);
            cpasync16(d + 1 * TILE * 2, gsrc1 + ko);
            cpasync16(d + 2 * TILE * 2, gsrc2 + ko);
            cpasync16(d + 3 * TILE * 2, gsrc3 + ko);
            asm volatile("cp.async.commit_group;");
            asm volatile("cp.async.wait_group 1;");
        } else {
            asm volatile("cp.async.wait_group 0;");
        }
        __syncthreads();

        const unsigned ub = sbase + (unsigned)((it & 1) * 4) * TILE * 2;
        const unsigned uAh = ub + 0 * TILE * 2;
        const unsigned uAl = ub + 1 * TILE * 2;
        const unsigned uBh = ub + 2 * TILE * 2;
        const unsigned uBl = ub + 3 * TILE * 2;

        unsigned fah[2][4], fal[2][4];
#pragma unroll
        for (int mt = 0; mt < 2; mt++) {
            int r0 = wm * 32 + mt * 16;
            unsigned addr = (unsigned)((r0 + a_row) * SROW + a_kh) * 2;
            ldsm4(fah[mt][0], fah[mt][1], fah[mt][2], fah[mt][3], uAh + addr);
            ldsm4(fal[mt][0], fal[mt][1], fal[mt][2], fal[mt][3], uAl + addr);
        }

#pragma unroll
        for (int np = 0; np < 4; np++) {
            int n0 = wn * 64 + np * 16;
            unsigned addr = (unsigned)((n0 + b_n) * SROW + b_kh) * 2;
            unsigned bh0, bh1, bh2, bh3, bl0, bl1, bl2, bl3;
            ldsm4(bh0, bh1, bh2, bh3, uBh + addr);
            ldsm4(bl0, bl1, bl2, bl3, uBl + addr);
#pragma unroll
            for (int mt = 0; mt < 2; mt++) {
                MMA16816(acc[mt][2 * np],     fah[mt][0], fah[mt][1], fah[mt][2], fah[mt][3], bh0, bh1);
                MMA16816(acc[mt][2 * np],     fal[mt][0], fal[mt][1], fal[mt][2], fal[mt][3], bh0, bh1);
                MMA16816(acc[mt][2 * np],     fah[mt][0], fah[mt][1], fah[mt][2], fah[mt][3], bl0, bl1);
                MMA16816(acc[mt][2 * np + 1], fah[mt][0], fah[mt][1], fah[mt][2], fah[mt][3], bh2, bh3);
                MMA16816(acc[mt][2 * np + 1], fal[mt][0], fal[mt][1], fal[mt][2], fal[mt][3], bh2, bh3);
                MMA16816(acc[mt][2 * np + 1], fah[mt][0], fah[mt][1], fah[mt][2], fah[mt][3], bl2, bl3);
            }
        }
        __syncthreads();
    }

    // epilogue: warp's 64-col span is entirely self or entirely neigh
    const int cg = colbase + wn * 64;
    float* base = (cg < Nself) ? Cs : Cn;
    const int c0 = (cg < Nself) ? cg : cg - Nself;

    const int g = lane >> 2, t = lane & 3;
#pragma unroll
    for (int mt = 0; mt < 2; mt++) {
#pragma unroll
        for (int nt = 0; nt < 8; nt++) {
            size_t r = rowbase + wm * 32 + mt * 16 + g;
            int c = c0 + nt * 8 + 2 * t;
            *(float2*)(base + r * Nself + c)       = make_float2(acc[mt][nt][0], acc[mt][nt][1]);
            *(float2*)(base + (r + 8) * Nself + c) = make_float2(acc[mt][nt][2], acc[mt][nt][3]);
        }
    }
}

// ---------------- aggregation + epilogue -----------------------------------
// Layer-1 agg is done in TWO passes over 64-column halves so the gather
// working set (25.6 MB) stays L2-resident. __ldcg on gathers (skip L1),
// __ldcs/__stcs on streamed data (evict-first; don't pollute L2).

__global__ void k_agg128_pass(const float* __restrict__ ys, const float* __restrict__ yn,
                              const float* __restrict__ bias,
                              __nv_bfloat16* __restrict__ ohi, __nv_bfloat16* __restrict__ olo,
                              int colOff)
{
    int w = (blockIdx.x * blockDim.x + threadIdx.x) >> 5;
    int lane = threadIdx.x & 31;
    if (w >= NN) return;
    int s0 = g_off[w], s1 = g_off[w + 1];
    const float2* p = (const float2*)yn;           // row = 64 float2
    const int cidx = (colOff >> 1) + lane;
    float2 a0 = make_float2(0.f, 0.f), a1 = a0, a2 = a0, a3 = a0;
    int e = s0;
    for (; e + 4 <= s1; e += 4) {
        int i0 = g_csr[e], i1 = g_csr[e + 1], i2 = g_csr[e + 2], i3 = g_csr[e + 3];
        float2 v0 = __ldcg(&p[(size_t)i0 * 64 + cidx]);
        float2 v1 = __ldcg(&p[(size_t)i1 * 64 + cidx]);
        float2 v2 = __ldcg(&p[(size_t)i2 * 64 + cidx]);
        float2 v3 = __ldcg(&p[(size_t)i3 * 64 + cidx]);
        a0.x += v0.x; a0.y += v0.y;
        a1.x += v1.x; a1.y += v1.y;
        a2.x += v2.x; a2.y += v2.y;
        a3.x += v3.x; a3.y += v3.y;
    }
    for (; e < s1; e++) {
        float2 v = __ldcg(&p[(size_t)g_csr[e] * 64 + cidx]);
        a0.x += v.x; a0.y += v.y;
    }
    float2 acc = make_float2((a0.x + a1.x) + (a2.x + a3.x),
                             (a0.y + a1.y) + (a2.y + a3.y));

    float inv = (s1 > s0) ? 1.f / (float)(s1 - s0) : 0.f;
    float2 sv = __ldcs((const float2*)ys + (size_t)w * 64 + cidx);
    float2 bb = ((const float2*)bias)[cidx];
    float ox = fmaxf(sv.x + acc.x * inv + bb.x, 0.f);
    float oy = fmaxf(sv.y + acc.y * inv + bb.y, 0.f);

    __nv_bfloat16 hx = __float2bfloat16(ox), hy = __float2bfloat16(oy);
    __nv_bfloat162 h01, l01;
    h01.x = hx; h01.y = hy;
    l01.x = __float2bfloat16(ox - __bfloat162float(hx));
    l01.y = __float2bfloat16(oy - __bfloat162float(hy));
    __stcs((unsigned*)(ohi + (size_t)w * 128 + colOff) + lane, *(unsigned*)&h01);
    __stcs((unsigned*)(olo + (size_t)w * 128 + colOff) + lane, *(unsigned*)&l01);
}

__global__ void k_agg64_relu(const float* __restrict__ ys, const float* __restrict__ yn,
                             const float* __restrict__ bias,
                             __nv_bfloat16* __restrict__ ohi, __nv_bfloat16* __restrict__ olo)
{
    int w = (blockIdx.x * blockDim.x + threadIdx.x) >> 5;
    int lane = threadIdx.x & 31;
    if (w >= NN) return;
    int s0 = g_off[w], s1 = g_off[w + 1];
    const float2* p = (const float2*)yn;       // row = 32 float2
    float2 a0 = make_float2(0.f, 0.f), a1 = a0, a2 = a0, a3 = a0;
    int e = s0;
    for (; e + 4 <= s1; e += 4) {
        int i0 = g_csr[e], i1 = g_csr[e + 1], i2 = g_csr[e + 2], i3 = g_csr[e + 3];
        float2 v0 = __ldcg(&p[(size_t)i0 * 32 + lane]);
        float2 v1 = __ldcg(&p[(size_t)i1 * 32 + lane]);
        float2 v2 = __ldcg(&p[(size_t)i2 * 32 + lane]);
        float2 v3 = __ldcg(&p[(size_t)i3 * 32 + lane]);
        a0.x += v0.x; a0.y += v0.y;
        a1.x += v1.x; a1.y += v1.y;
        a2.x += v2.x; a2.y += v2.y;
        a3.x += v3.x; a3.y += v3.y;
    }
    for (; e < s1; e++) {
        float2 v = __ldcg(&p[(size_t)g_csr[e] * 32 + lane]);
        a0.x += v.x; a0.y += v.y;
    }
    float2 acc = make_float2((a0.x + a1.x) + (a2.x + a3.x),
                             (a0.y + a1.y) + (a2.y + a3.y));

    float inv = (s1 > s0) ? 1.f / (float)(s1 - s0) : 0.f;
    float2 sv = __ldcs((const float2*)ys + (size_t)w * 32 + lane);
    float2 bb = ((const float2*)bias)[lane];
    float ox = fmaxf(sv.x + acc.x * inv + bb.x, 0.f);
    float oy = fmaxf(sv.y + acc.y * inv + bb.y, 0.f);

    __nv_bfloat16 hx = __float2bfloat16(ox), hy = __float2bfloat16(oy);
    __nv_bfloat162 h01, l01;
    h01.x = hx; h01.y = hy;
    l01.x = __float2bfloat16(ox - __bfloat162float(hx));
    l01.y = __float2bfloat16(oy - __bfloat162float(hy));
    __stcs((unsigned*)(ohi + (size_t)w * 64) + lane, *(unsigned*)&h01);
    __stcs((unsigned*)(olo + (size_t)w * 64) + lane, *(unsigned*)&l01);
}

__global__ void k_agg64_softmax(const float* __restrict__ ys, const float* __restrict__ yn,
                                const float* __restrict__ bias, float* __restrict__ out)
{
    int w = (blockIdx.x * blockDim.x + threadIdx.x) >> 5;
    int lane = threadIdx.x & 31;
    if (w >= NN) return;
    int s0 = g_off[w], s1 = g_off[w + 1];
    const float2* p = (const float2*)yn;
    float2 a0 = make_float2(0.f, 0.f), a1 = a0, a2 = a0, a3 = a0;
    int e = s0;
    for (; e + 4 <= s1; e += 4) {
        int i0 = g_csr[e], i1 = g_csr[e + 1], i2 = g_csr[e + 2], i3 = g_csr[e + 3];
        float2 v0 = __ldcg(&p[(size_t)i0 * 32 + lane]);
        float2 v1 = __ldcg(&p[(size_t)i1 * 32 + lane]);
        float2 v2 = __ldcg(&p[(size_t)i2 * 32 + lane]);
        float2 v3 = __ldcg(&p[(size_t)i3 * 32 + lane]);
        a0.x += v0.x; a0.y += v0.y;
        a1.x += v1.x; a1.y += v1.y;
        a2.x += v2.x; a2.y += v2.y;
        a3.x += v3.x; a3.y += v3.y;
    }
    for (; e < s1; e++) {
        float2 v = __ldcg(&p[(size_t)g_csr[e] * 32 + lane]);
        a0.x += v.x; a0.y += v.y;
    }
    float2 acc = make_float2((a0.x + a1.x) + (a2.x + a3.x),
                             (a0.y + a1.y) + (a2.y + a3.y));

    float inv = (s1 > s0) ? 1.f / (float)(s1 - s0) : 0.f;
    float2 sv = __ldcs((const float2*)ys + (size_t)w * 32 + lane);
    float2 bb = ((const float2*)bias)[lane];
    float vx = sv.x + acc.x * inv + bb.x;
    float vy = sv.y + acc.y * inv + bb.y;

    float m = fmaxf(vx, vy);
#pragma unroll
    for (int o = 16; o > 0; o >>= 1)
        m = fmaxf(m, __shfl_xor_sync(0xffffffffu, m, o));
    float ex = __expf(vx - m);
    float ey = __expf(vy - m);
    float s = ex + ey;
#pragma unroll
    for (int o = 16; o > 0; o >>= 1)
        s += __shfl_xor_sync(0xffffffffu, s, o);
    float r = 1.f / s;
    ((float2*)out)[(size_t)w * 32 + lane] = make_float2(ex * r, ey * r);
}

// ---------------- launch ----------------------------------------------------
extern "C" void kernel_launch(void* const* d_in, const int* in_sizes, int n_in,
                              void* d_out, int out_size)
{
    const float* x   = (const float*)d_in[0];
    const int*   src = (const int*)d_in[1];
    const int*   dst = (const int*)d_in[2];
    const float* w1s = (const float*)d_in[3];
    const float* w1n = (const float*)d_in[4];
    const float* b1  = (const float*)d_in[5];
    const float* w2s = (const float*)d_in[6];
    const float* w2n = (const float*)d_in[7];
    const float* b2  = (const float*)d_in[8];
    const float* w3s = (const float*)d_in[9];
    const float* w3n = (const float*)d_in[10];
    const float* b3  = (const float*)d_in[11];
    float* out = (float*)d_out;
    int E = in_sizes[1];
    if (E > EMAX) E = EMAX;

    __nv_bfloat16 *p_ahi, *p_alo;
    float *p_ys, *p_yn;
    cudaGetSymbolAddress((void**)&p_ahi, g_ahi);
    cudaGetSymbolAddress((void**)&p_alo, g_alo);
    cudaGetSymbolAddress((void**)&p_ys, g_ys);
    cudaGetSymbolAddress((void**)&p_yn, g_yn);

    const int MB = NPAD / 128;                    // 782
    const int AGG_BLKS = (NN * 32 + 255) / 256;   // 12500
    const int E4 = (E + 3) / 4;

    // Layer 1 (GEMM at launch index 3 for the ncu window)
    k_split4<<<(NN * 128 / 4 + 255) / 256, 256>>>(x, NN * 128 / 4);
    k_pack<<<(2 * 128 * 128 + 255) / 256, 256>>>(w1s, w1n, 128, 128);
    k_zero_deg<<<256, 256>>>();
    k_gemm_mma<<<dim3(MB, 2), 256>>>(p_ahi, p_alo, p_ys, p_yn, 128, 128);
    k_count<<<(E4 + 255) / 256, 256>>>(dst, E);
    k_scan<<<1, 1024>>>();
    k_scatter<<<(E4 + 255) / 256, 256>>>(src, dst, E);
    k_agg128_pass<<<AGG_BLKS, 256>>>(p_ys, p_yn, b1, p_ahi, p_alo, 0);
    k_agg128_pass<<<AGG_BLKS, 256>>>(p_ys, p_yn, b1, p_ahi, p_alo, 64);

    // Layer 2: 128 -> 64 (2N = 128)
    k_pack<<<(2 * 64 * 128 + 255) / 256, 256>>>(w2s, w2n, 128, 64);
    k_gemm_mma<<<dim3(MB, 1), 256>>>(p_ahi, p_alo, p_ys, p_yn, 128, 64);
    k_agg64_relu<<<AGG_BLKS, 256>>>(p_ys, p_yn, b2, p_ahi, p_alo);

    // Layer 3: 64 -> 64 (2N = 128) + softmax
    k_pack<<<(2 * 64 * 64 + 255) / 256, 256>>>(w3s, w3n, 64, 64);
    k_gemm_mma<<<dim3(MB, 1), 256>>>(p_ahi, p_alo, p_ys, p_yn, 64, 64);
    k_agg64_softmax<<<AGG_BLKS, 256>>>(p_ys, p_yn, b3, out);
}

// round 10
// speedup vs baseline: 1.0757x; 1.0757x over previous
#include <cuda_runtime.h>
#include <cuda_bf16.h>

#define NN   100000
#define NPAD 100096            // 782 * 128
#define EMAX 1600000
#define SROW 24                // smem row stride (bf16 elems); 48B -> conflict-free ldmatrix

// ---------------- scratch (device globals; no allocation allowed) ----------
__device__ __nv_bfloat16 g_ahi[(size_t)NPAD * 128];
__device__ __nv_bfloat16 g_alo[(size_t)NPAD * 128];
__device__ float         g_y  [(size_t)NPAD * 256];   // GEMM output [ys | yn]
__device__ __nv_bfloat16 g_bthi[256 * 128];           // packed B^T hi  [2N][K]
__device__ __nv_bfloat16 g_btlo[256 * 128];           // packed B^T lo
__device__ int g_deg[NN];
__device__ int g_off[NN + 1];
__device__ int g_cur[NN];
__device__ int g_csr[EMAX];

// ---------------- CSR build -------------------------------------------------
__global__ void k_zero_deg() {
    for (int i = blockIdx.x * blockDim.x + threadIdx.x; i < NN;
         i += gridDim.x * blockDim.x)
        g_deg[i] = 0;
}

__global__ void k_count(const int* __restrict__ dst, int E) {
    int i0 = (blockIdx.x * blockDim.x + threadIdx.x) * 4;
    if (i0 + 3 < E) {
        int4 d = *(const int4*)(dst + i0);
        atomicAdd(&g_deg[d.x], 1);
        atomicAdd(&g_deg[d.y], 1);
        atomicAdd(&g_deg[d.z], 1);
        atomicAdd(&g_deg[d.w], 1);
    } else {
        for (int j = 0; j < 4; j++) {
            int i = i0 + j;
            if (i < E) atomicAdd(&g_deg[dst[i]], 1);
        }
    }
}

__global__ void k_scan() {
    __shared__ int ss[1024];
    int t = threadIdx.x;
    const int CH = (NN + 1023) / 1024;
    int beg = t * CH; if (beg > NN) beg = NN;
    int end = beg + CH; if (end > NN) end = NN;
    int s = 0;
    for (int i = beg; i < end; i++) s += g_deg[i];
    ss[t] = s;
    __syncthreads();
    for (int d = 1; d < 1024; d <<= 1) {
        int v = (t >= d) ? ss[t - d] : 0;
        __syncthreads();
        ss[t] += v;
        __syncthreads();
    }
    int run = ss[t] - s;
    for (int i = beg; i < end; i++) {
        g_off[i] = run;
        g_cur[i] = run;
        run += g_deg[i];
    }
    if (t == 1023) g_off[NN] = ss[1023];
}

__global__ void k_scatter(const int* __restrict__ src, const int* __restrict__ dst, int E) {
    int i0 = (blockIdx.x * blockDim.x + threadIdx.x) * 4;
    if (i0 + 3 < E) {
        int4 d = *(const int4*)(dst + i0);
        int4 s = *(const int4*)(src + i0);
        int p0 = atomicAdd(&g_cur[d.x], 1);
        int p1 = atomicAdd(&g_cur[d.y], 1);
        int p2 = atomicAdd(&g_cur[d.z], 1);
        int p3 = atomicAdd(&g_cur[d.w], 1);
        g_csr[p0] = s.x; g_csr[p1] = s.y; g_csr[p2] = s.z; g_csr[p3] = s.w;
    } else {
        for (int j = 0; j < 4; j++) {
            int i = i0 + j;
            if (i < E) {
                int p = atomicAdd(&g_cur[dst[i]], 1);
                g_csr[p] = src[i];
            }
        }
    }
}

// ---------------- weight pack: [Ws | Wn] -> B^T bf16 hi/lo -----------------
__global__ void k_pack(const float* __restrict__ ws, const float* __restrict__ wn,
                       int K, int N)
{
    int idx = blockIdx.x * blockDim.x + threadIdx.x;
    int total = 2 * N * K;
    if (idx >= total) return;
    int n = idx / K, k = idx - n * K;
    float v = (n < N) ? ws[k * N + n] : wn[k * N + (n - N)];
    __nv_bfloat16 h = __float2bfloat16(v);
    g_bthi[n * K + k] = h;
    g_btlo[n * K + k] = __float2bfloat16(v - __bfloat162float(h));
}

// ---------------- fp32 -> bf16 hi/lo split of the input features -----------
__global__ void k_split4(const float* __restrict__ x, int n4) {
    int i = blockIdx.x * blockDim.x + threadIdx.x;
    if (i >= n4) return;
    float4 v = ((const float4*)x)[i];
    __nv_bfloat16 hx = __float2bfloat16(v.x), hy = __float2bfloat16(v.y);
    __nv_bfloat16 hz = __float2bfloat16(v.z), hw = __float2bfloat16(v.w);
    __nv_bfloat162 h01, h23, l01, l23;
    h01.x = hx; h01.y = hy; h23.x = hz; h23.y = hw;
    l01.x = __float2bfloat16(v.x - __bfloat162float(hx));
    l01.y = __float2bfloat16(v.y - __bfloat162float(hy));
    l23.x = __float2bfloat16(v.z - __bfloat162float(hz));
    l23.y = __float2bfloat16(v.w - __bfloat162float(hw));
    uint2 hp, lp;
    hp.x = *(unsigned*)&h01; hp.y = *(unsigned*)&h23;
    lp.x = *(unsigned*)&l01; lp.y = *(unsigned*)&l23;
    ((uint2*)g_ahi)[i] = hp;
    ((uint2*)g_alo)[i] = lp;
}

// ---------------- tensor-core GEMM (split bf16, 3 products, pipelined) ------
#define MMA16816(d, a0, a1, a2, a3, b0, b1)                                    \
    asm volatile(                                                              \
        "mma.sync.aligned.m16n8k16.row.col.f32.bf16.bf16.f32 "                 \
        "{%0,%1,%2,%3}, {%4,%5,%6,%7}, {%8,%9}, {%0,%1,%2,%3};"               \
        : "+f"(d[0]), "+f"(d[1]), "+f"(d[2]), "+f"(d[3])                       \
        : "r"(a0), "r"(a1), "r"(a2), "r"(a3), "r"(b0), "r"(b1))

__device__ __forceinline__ void ldsm4(unsigned& r0, unsigned& r1,
                                      unsigned& r2, unsigned& r3, unsigned addr) {
    asm volatile("ldmatrix.sync.aligned.m8n8.x4.shared.b16 {%0,%1,%2,%3}, [%4];"
                 : "=r"(r0), "=r"(r1), "=r"(r2), "=r"(r3) : "r"(addr));
}

__device__ __forceinline__ void cpasync16(unsigned dst, const void* src) {
    asm volatile("cp.async.ca.shared.global [%0], [%1], 16;" :: "r"(dst), "l"(src));
}

// C[M,2N] = A[M,K] * Bt[2N,K]^T. Block tile 128x128, 8 warps (4m x 2n),
// warp tile 32x64. BK=32 two-subtile stages, 2-stage double buffer,
// one sync pair per 32 k. Joint output layout (ldc = 2N).
__global__ __launch_bounds__(256, 2)
void k_gemm_mma(const __nv_bfloat16* __restrict__ Ahi,
                const __nv_bfloat16* __restrict__ Alo,
                float* __restrict__ C, int K, int ldc)
{
    extern __shared__ __align__(16) __nv_bfloat16 sm[];
    const int SUB = 128 * SROW;     // elems per 16-k subtile
    const int ARR = 2 * SUB;        // per array (2 subtiles)
    const int STG = 4 * ARR;        // per stage (Ah, Al, Bh, Bl)

    const int tid = threadIdx.x;
    const int warp = tid >> 5, lane = tid & 31;
    const int wm = warp & 3, wn = warp >> 2;
    const size_t rowbase = (size_t)blockIdx.x * 128;
    const size_t colbase = (size_t)blockIdx.y * 128;

    // cp.async mapping per subtile: 128 rows x 16 k, one 16B op per thread
    const int lr = tid >> 1;
    const int lc = (tid & 1) * 8;

    const unsigned sbase = (unsigned)__cvta_generic_to_shared(sm);
    const unsigned sdst = sbase + (unsigned)(lr * SROW + lc) * 2;

    const __nv_bfloat16* gA0 = Ahi    + (rowbase + lr) * K + lc;
    const __nv_bfloat16* gA1 = Alo    + (rowbase + lr) * K + lc;
    const __nv_bfloat16* gB0 = g_bthi + (colbase + lr) * K + lc;
    const __nv_bfloat16* gB1 = g_btlo + (colbase + lr) * K + lc;

    float acc[2][8][4];
#pragma unroll
    for (int i = 0; i < 2; i++)
#pragma unroll
        for (int j = 0; j < 8; j++)
#pragma unroll
            for (int q = 0; q < 4; q++) acc[i][j][q] = 0.f;

    const int KT2 = K >> 5;         // 32-k stages

    // stage load: 8 cp.async per thread (4 arrays x 2 subtiles), one commit
#define LOAD_STAGE(buf, kk)                                                    \
    do {                                                                       \
        unsigned b_ = sdst + (unsigned)(buf) * STG * 2;                        \
        _Pragma("unroll")                                                      \
        for (int sub_ = 0; sub_ < 2; sub_++) {                                 \
            int ko_ = (kk) + sub_ * 16;                                        \
            unsigned so_ = (unsigned)sub_ * SUB * 2;                           \
            cpasync16(b_ + 0u * ARR * 2 + so_, gA0 + ko_);                     \
            cpasync16(b_ + 1u * ARR * 2 + so_, gA1 + ko_);                     \
            cpasync16(b_ + 2u * ARR * 2 + so_, gB0 + ko_);                     \
            cpasync16(b_ + 3u * ARR * 2 + so_, gB1 + ko_);                     \
        }                                                                      \
        asm volatile("cp.async.commit_group;");                                \
    } while (0)

    LOAD_STAGE(0, 0);

    // per-lane fragment address pieces
    const int a_row = (lane & 15);
    const int a_kh  = (lane >> 4) * 8;
    const int b_n   = (lane & 7) + (lane >> 4) * 8;
    const int b_kh  = ((lane >> 3) & 1) * 8;

    for (int it = 0; it < KT2; it++) {
        if (it + 1 < KT2) {
            LOAD_STAGE((it + 1) & 1, (it + 1) * 32);
            asm volatile("cp.async.wait_group 1;");
        } else {
            asm volatile("cp.async.wait_group 0;");
        }
        __syncthreads();

        const unsigned ub = sbase + (unsigned)(it & 1) * STG * 2;
#pragma unroll
        for (int sub = 0; sub < 2; sub++) {
            const unsigned so  = (unsigned)sub * SUB * 2;
            const unsigned uAh = ub + 0u * ARR * 2 + so;
            const unsigned uAl = ub + 1u * ARR * 2 + so;
            const unsigned uBh = ub + 2u * ARR * 2 + so;
            const unsigned uBl = ub + 3u * ARR * 2 + so;

            unsigned fah[2][4], fal[2][4];
#pragma unroll
            for (int mt = 0; mt < 2; mt++) {
                int r0 = wm * 32 + mt * 16;
                unsigned addr = (unsigned)((r0 + a_row) * SROW + a_kh) * 2;
                ldsm4(fah[mt][0], fah[mt][1], fah[mt][2], fah[mt][3], uAh + addr);
                ldsm4(fal[mt][0], fal[mt][1], fal[mt][2], fal[mt][3], uAl + addr);
            }

#pragma unroll
            for (int np = 0; np < 4; np++) {
                int n0 = wn * 64 + np * 16;
                unsigned addr = (unsigned)((n0 + b_n) * SROW + b_kh) * 2;
                unsigned bh0, bh1, bh2, bh3, bl0, bl1, bl2, bl3;
                ldsm4(bh0, bh1, bh2, bh3, uBh + addr);
                ldsm4(bl0, bl1, bl2, bl3, uBl + addr);
#pragma unroll
                for (int mt = 0; mt < 2; mt++) {
                    MMA16816(acc[mt][2 * np],     fah[mt][0], fah[mt][1], fah[mt][2], fah[mt][3], bh0, bh1);
                    MMA16816(acc[mt][2 * np],     fal[mt][0], fal[mt][1], fal[mt][2], fal[mt][3], bh0, bh1);
                    MMA16816(acc[mt][2 * np],     fah[mt][0], fah[mt][1], fah[mt][2], fah[mt][3], bl0, bl1);
                    MMA16816(acc[mt][2 * np + 1], fah[mt][0], fah[mt][1], fah[mt][2], fah[mt][3], bh2, bh3);
                    MMA16816(acc[mt][2 * np + 1], fal[mt][0], fal[mt][1], fal[mt][2], fal[mt][3], bh2, bh3);
                    MMA16816(acc[mt][2 * np + 1], fah[mt][0], fah[mt][1], fah[mt][2], fah[mt][3], bl2, bl3);
                }
            }
        }
        __syncthreads();
    }

    const int g = lane >> 2, t = lane & 3;
#pragma unroll
    for (int mt = 0; mt < 2; mt++) {
#pragma unroll
        for (int nt = 0; nt < 8; nt++) {
            size_t r = rowbase + wm * 32 + mt * 16 + g;
            size_t c = colbase + wn * 64 + nt * 8 + 2 * t;
            *(float2*)(C + r * ldc + c)       = make_float2(acc[mt][nt][0], acc[mt][nt][1]);
            *(float2*)(C + (r + 8) * ldc + c) = make_float2(acc[mt][nt][2], acc[mt][nt][3]);
        }
    }
#undef LOAD_STAGE
}

// ---------------- aggregation + epilogue -----------------------------------
// y layout: [NPAD][2d] fp32, self = cols [0,d), neigh = cols [d,2d).
// Outputs bf16 hi/lo split (feeds next GEMM). (Proven R5 design.)

__global__ void k_agg128_relu(const float* __restrict__ y, const float* __restrict__ bias,
                              __nv_bfloat16* __restrict__ ohi, __nv_bfloat16* __restrict__ olo)
{
    int w = (blockIdx.x * blockDim.x + threadIdx.x) >> 5;
    int lane = threadIdx.x & 31;
    if (w >= NN) return;
    int s0 = g_off[w], s1 = g_off[w + 1];
    const float4* y4 = (const float4*)y;       // row stride = 64 float4
    float4 acc = make_float4(0.f, 0.f, 0.f, 0.f);
    for (int e = s0; e < s1; e++) {
        int s = g_csr[e];
        float4 v = y4[(size_t)s * 64 + 32 + lane];
        acc.x += v.x; acc.y += v.y; acc.z += v.z; acc.w += v.w;
    }
    float inv = (s1 > s0) ? 1.f / (float)(s1 - s0) : 0.f;
    float4 sv = y4[(size_t)w * 64 + lane];
    float4 bb = ((const float4*)bias)[lane];
    float4 o;
    o.x = fmaxf(sv.x + acc.x * inv + bb.x, 0.f);
    o.y = fmaxf(sv.y + acc.y * inv + bb.y, 0.f);
    o.z = fmaxf(sv.z + acc.z * inv + bb.z, 0.f);
    o.w = fmaxf(sv.w + acc.w * inv + bb.w, 0.f);

    __nv_bfloat16 hx = __float2bfloat16(o.x), hy = __float2bfloat16(o.y);
    __nv_bfloat16 hz = __float2bfloat16(o.z), hw = __float2bfloat16(o.w);
    __nv_bfloat162 h01, h23, l01, l23;
    h01.x = hx; h01.y = hy; h23.x = hz; h23.y = hw;
    l01.x = __float2bfloat16(o.x - __bfloat162float(hx));
    l01.y = __float2bfloat16(o.y - __bfloat162float(hy));
    l23.x = __float2bfloat16(o.z - __bfloat162float(hz));
    l23.y = __float2bfloat16(o.w - __bfloat162float(hw));
    uint2 hp, lp;
    hp.x = *(unsigned*)&h01; hp.y = *(unsigned*)&h23;
    lp.x = *(unsigned*)&l01; lp.y = *(unsigned*)&l23;
    *(uint2*)(ohi + (size_t)w * 128 + lane * 4) = hp;
    *(uint2*)(olo + (size_t)w * 128 + lane * 4) = lp;
}

__global__ void k_agg64_relu(const float* __restrict__ y, const float* __restrict__ bias,
                             __nv_bfloat16* __restrict__ ohi, __nv_bfloat16* __restrict__ olo)
{
    int w = (blockIdx.x * blockDim.x + threadIdx.x) >> 5;
    int lane = threadIdx.x & 31;
    if (w >= NN) return;
    int s0 = g_off[w], s1 = g_off[w + 1];
    const float2* y2 = (const float2*)y;       // row stride = 64 float2
    float2 acc = make_float2(0.f, 0.f);
    for (int e = s0; e < s1; e++) {
        int s = g_csr[e];
        float2 v = y2[(size_t)s * 64 + 32 + lane];
        acc.x += v.x; acc.y += v.y;
    }
    float inv = (s1 > s0) ? 1.f / (float)(s1 - s0) : 0.f;
    float2 sv = y2[(size_t)w * 64 + lane];
    float2 bb = ((const float2*)bias)[lane];
    float ox = fmaxf(sv.x + acc.x * inv + bb.x, 0.f);
    float oy = fmaxf(sv.y + acc.y * inv + bb.y, 0.f);

    __nv_bfloat16 hx = __float2bfloat16(ox), hy = __float2bfloat16(oy);
    __nv_bfloat162 h01, l01;
    h01.x = hx; h01.y = hy;
    l01.x = __float2bfloat16(ox - __bfloat162float(hx));
    l01.y = __float2bfloat16(oy - __bfloat162float(hy));
    *(unsigned*)(ohi + (size_t)w * 64 + lane * 2) = *(unsigned*)&h01;
    *(unsigned*)(olo + (size_t)w * 64 + lane * 2) = *(unsigned*)&l01;
}

__global__ void k_agg64_softmax(const float* __restrict__ y, const float* __restrict__ bias,
                                float* __restrict__ out)
{
    int w = (blockIdx.x * blockDim.x + threadIdx.x) >> 5;
    int lane = threadIdx.x & 31;
    if (w >= NN) return;
    int s0 = g_off[w], s1 = g_off[w + 1];
    const float2* y2 = (const float2*)y;
    float2 acc = make_float2(0.f, 0.f);
    for (int e = s0; e < s1; e++) {
        int s = g_csr[e];
        float2 v = y2[(size_t)s * 64 + 32 + lane];
        acc.x += v.x; acc.y += v.y;
    }
    float inv = (s1 > s0) ? 1.f / (float)(s1 - s0) : 0.f;
    float2 sv = y2[(size_t)w * 64 + lane];
    float2 bb = ((const float2*)bias)[lane];
    float vx = sv.x + acc.x * inv + bb.x;
    float vy = sv.y + acc.y * inv + bb.y;

    float m = fmaxf(vx, vy);
#pragma unroll
    for (int o = 16; o > 0; o >>= 1)
        m = fmaxf(m, __shfl_xor_sync(0xffffffffu, m, o));
    float ex = __expf(vx - m);
    float ey = __expf(vy - m);
    float s = ex + ey;
#pragma unroll
    for (int o = 16; o > 0; o >>= 1)
        s += __shfl_xor_sync(0xffffffffu, s, o);
    float r = 1.f / s;
    ((float2*)out)[(size_t)w * 32 + lane] = make_float2(ex * r, ey * r);
}

// ---------------- launch ----------------------------------------------------
extern "C" void kernel_launch(void* const* d_in, const int* in_sizes, int n_in,
                              void* d_out, int out_size)
{
    const float* x   = (const float*)d_in[0];
    const int*   src = (const int*)d_in[1];
    const int*   dst = (const int*)d_in[2];
    const float* w1s = (const float*)d_in[3];
    const float* w1n = (const float*)d_in[4];
    const float* b1  = (const float*)d_in[5];
    const float* w2s = (const float*)d_in[6];
    const float* w2n = (const float*)d_in[7];
    const float* b2  = (const float*)d_in[8];
    const float* w3s = (const float*)d_in[9];
    const float* w3n = (const float*)d_in[10];
    const float* b3  = (const float*)d_in[11];
    float* out = (float*)d_out;
    int E = in_sizes[1];
    if (E > EMAX) E = EMAX;

    __nv_bfloat16 *p_ahi, *p_alo;
    float* p_y;
    cudaGetSymbolAddress((void**)&p_ahi, g_ahi);
    cudaGetSymbolAddress((void**)&p_alo, g_alo);
    cudaGetSymbolAddress((void**)&p_y, g_y);

    // dynamic smem: 2 stages x 4 arrays x 2 subtiles x 128 x SROW bf16
    const int SMEMB = 2 * 4 * 2 * 128 * SROW * 2;   // 98304 B
    static int attr_done = 0;
    if (!attr_done) {
        cudaFuncSetAttribute(k_gemm_mma, cudaFuncAttributeMaxDynamicSharedMemorySize, SMEMB);
        attr_done = 1;
    }

    const int MB = NPAD / 128;                    // 782
    const int AGG_BLKS = (NN * 32 + 255) / 256;   // 12500
    const int E4 = (E + 3) / 4;

    // Layer 1 (GEMM at launch index 3 for the ncu window)
    k_split4<<<(NN * 128 / 4 + 255) / 256, 256>>>(x, NN * 128 / 4);
    k_pack<<<(2 * 128 * 128 + 255) / 256, 256>>>(w1s, w1n, 128, 128);
    k_zero_deg<<<256, 256>>>();
    k_gemm_mma<<<dim3(MB, 2), 256, SMEMB>>>(p_ahi, p_alo, p_y, 128, 256);
    k_count<<<(E4 + 255) / 256, 256>>>(dst, E);
    k_scan<<<1, 1024>>>();
    k_scatter<<<(E4 + 255) / 256, 256>>>(src, dst, E);
    k_agg128_relu<<<AGG_BLKS, 256>>>(p_y, b1, p_ahi, p_alo);

    // Layer 2: 128 -> 64 (2N = 128)
    k_pack<<<(2 * 64 * 128 + 255) / 256, 256>>>(w2s, w2n, 128, 64);
    k_gemm_mma<<<dim3(MB, 1), 256, SMEMB>>>(p_ahi, p_alo, p_y, 128, 128);
    k_agg64_relu<<<AGG_BLKS, 256>>>(p_y, b2, p_ahi, p_alo);

    // Layer 3: 64 -> 64 (2N = 128) + softmax
    k_pack<<<(2 * 64 * 64 + 255) / 256, 256>>>(w3s, w3n, 64, 64);
    k_gemm_mma<<<dim3(MB, 1), 256, SMEMB>>>(p_ahi, p_alo, p_y, 64, 128);
    k_agg64_softmax<<<AGG_BLKS, 256>>>(p_y, b3, out);
}

// round 12
// speedup vs baseline: 1.0951x; 1.0180x over previous
#include <cuda_runtime.h>
#include <cuda_bf16.h>

#define NN   100000
#define NPAD 100096            // 782 * 128
#define EMAX 1600000
#define SROW 24                // smem row stride (bf16 elems); 48B -> conflict-free ldmatrix

// ---------------- scratch (device globals; no allocation allowed) ----------
__device__ __nv_bfloat16 g_ahi[(size_t)NPAD * 128];
__device__ __nv_bfloat16 g_alo[(size_t)NPAD * 128];
__device__ float         g_y  [(size_t)NPAD * 256];   // GEMM output [ys | yn]
__device__ __nv_bfloat16 g_bthi[256 * 128];           // packed B^T hi  [2N][K]
__device__ __nv_bfloat16 g_btlo[256 * 128];           // packed B^T lo
__device__ int g_deg[NN];
__device__ int g_off[NN + 1];
__device__ int g_cur[NN];
__device__ int g_csr[EMAX];

// ---------------- CSR build -------------------------------------------------
__global__ void k_zero_deg() {
    for (int i = blockIdx.x * blockDim.x + threadIdx.x; i < NN;
         i += gridDim.x * blockDim.x)
        g_deg[i] = 0;
}

__global__ void k_count(const int* __restrict__ dst, int E) {
    int i0 = (blockIdx.x * blockDim.x + threadIdx.x) * 4;
    if (i0 + 3 < E) {
        int4 d = *(const int4*)(dst + i0);
        atomicAdd(&g_deg[d.x], 1);
        atomicAdd(&g_deg[d.y], 1);
        atomicAdd(&g_deg[d.z], 1);
        atomicAdd(&g_deg[d.w], 1);
    } else {
        for (int j = 0; j < 4; j++) {
            int i = i0 + j;
            if (i < E) atomicAdd(&g_deg[dst[i]], 1);
        }
    }
}

__global__ void k_scan() {
    __shared__ int ss[1024];
    int t = threadIdx.x;
    const int CH = (NN + 1023) / 1024;
    int beg = t * CH; if (beg > NN) beg = NN;
    int end = beg + CH; if (end > NN) end = NN;
    int s = 0;
    for (int i = beg; i < end; i++) s += g_deg[i];
    ss[t] = s;
    __syncthreads();
    for (int d = 1; d < 1024; d <<= 1) {
        int v = (t >= d) ? ss[t - d] : 0;
        __syncthreads();
        ss[t] += v;
        __syncthreads();
    }
    int run = ss[t] - s;
    for (int i = beg; i < end; i++) {
        g_off[i] = run;
        g_cur[i] = run;
        run += g_deg[i];
    }
    if (t == 1023) g_off[NN] = ss[1023];
}

__global__ void k_scatter(const int* __restrict__ src, const int* __restrict__ dst, int E) {
    int i0 = (blockIdx.x * blockDim.x + threadIdx.x) * 4;
    if (i0 + 3 < E) {
        int4 d = *(const int4*)(dst + i0);
        int4 s = *(const int4*)(src + i0);
        int p0 = atomicAdd(&g_cur[d.x], 1);
        int p1 = atomicAdd(&g_cur[d.y], 1);
        int p2 = atomicAdd(&g_cur[d.z], 1);
        int p3 = atomicAdd(&g_cur[d.w], 1);
        g_csr[p0] = s.x; g_csr[p1] = s.y; g_csr[p2] = s.z; g_csr[p3] = s.w;
    } else {
        for (int j = 0; j < 4; j++) {
            int i = i0 + j;
            if (i < E) {
                int p = atomicAdd(&g_cur[dst[i]], 1);
                g_csr[p] = src[i];
            }
        }
    }
}

// ---------------- weight pack: [Ws | Wn] -> B^T bf16 hi/lo -----------------
__global__ void k_pack(const float* __restrict__ ws, const float* __restrict__ wn,
                       int K, int N)
{
    int idx = blockIdx.x * blockDim.x + threadIdx.x;
    int total = 2 * N * K;
    if (idx >= total) return;
    int n = idx / K, k = idx - n * K;
    float v = (n < N) ? ws[k * N + n] : wn[k * N + (n - N)];
    __nv_bfloat16 h = __float2bfloat16(v);
    g_bthi[n * K + k] = h;
    g_btlo[n * K + k] = __float2bfloat16(v - __bfloat162float(h));
}

// ---------------- fp32 -> bf16 hi/lo split of the input features -----------
__global__ void k_split4(const float* __restrict__ x, int n4) {
    int i = blockIdx.x * blockDim.x + threadIdx.x;
    if (i >= n4) return;
    float4 v = ((const float4*)x)[i];
    __nv_bfloat16 hx = __float2bfloat16(v.x), hy = __float2bfloat16(v.y);
    __nv_bfloat16 hz = __float2bfloat16(v.z), hw = __float2bfloat16(v.w);
    __nv_bfloat162 h01, h23, l01, l23;
    h01.x = hx; h01.y = hy; h23.x = hz; h23.y = hw;
    l01.x = __float2bfloat16(v.x - __bfloat162float(hx));
    l01.y = __float2bfloat16(v.y - __bfloat162float(hy));
    l23.x = __float2bfloat16(v.z - __bfloat162float(hz));
    l23.y = __float2bfloat16(v.w - __bfloat162float(hw));
    uint2 hp, lp;
    hp.x = *(unsigned*)&h01; hp.y = *(unsigned*)&h23;
    lp.x = *(unsigned*)&l01; lp.y = *(unsigned*)&l23;
    ((uint2*)g_ahi)[i] = hp;
    ((uint2*)g_alo)[i] = lp;
}

// ---------------- tensor-core GEMM (split bf16, 3 products, pipelined) ------
// (EXACT R5 design — empirically fastest of all variants tried: 77.9-78.8us)
#define MMA16816(d, a0, a1, a2, a3, b0, b1)                                    \
    asm volatile(                                                              \
        "mma.sync.aligned.m16n8k16.row.col.f32.bf16.bf16.f32 "                 \
        "{%0,%1,%2,%3}, {%4,%5,%6,%7}, {%8,%9}, {%0,%1,%2,%3};"               \
        : "+f"(d[0]), "+f"(d[1]), "+f"(d[2]), "+f"(d[3])                       \
        : "r"(a0), "r"(a1), "r"(a2), "r"(a3), "r"(b0), "r"(b1))

__device__ __forceinline__ void ldsm4(unsigned& r0, unsigned& r1,
                                      unsigned& r2, unsigned& r3, unsigned addr) {
    asm volatile("ldmatrix.sync.aligned.m8n8.x4.shared.b16 {%0,%1,%2,%3}, [%4];"
                 : "=r"(r0), "=r"(r1), "=r"(r2), "=r"(r3) : "r"(addr));
}

__device__ __forceinline__ void cpasync16(unsigned dst, const void* src) {
    asm volatile("cp.async.ca.shared.global [%0], [%1], 16;" :: "r"(dst), "l"(src));
}

// C[M,2N] = A[M,K] * Bt[2N,K]^T. Block tile 128x128, 8 warps (4m x 2n),
// warp tile 32x64. 2-stage cp.async double buffer, ldmatrix fragment loads.
__global__ __launch_bounds__(256, 2)
void k_gemm_mma(const __nv_bfloat16* __restrict__ Ahi,
                const __nv_bfloat16* __restrict__ Alo,
                float* __restrict__ C, int K, int ldc)
{
    __shared__ __align__(16) __nv_bfloat16 sm[2 * 4 * 128 * SROW];
    const int TILE = 128 * SROW;                // elems per tile

    const int tid = threadIdx.x;
    const int warp = tid >> 5, lane = tid & 31;
    const int wm = warp & 3, wn = warp >> 2;
    const size_t rowbase = (size_t)blockIdx.x * 128;
    const size_t colbase = (size_t)blockIdx.y * 128;

    const int lr = tid >> 1;
    const int lc = (tid & 1) * 8;

    const unsigned sbase = (unsigned)__cvta_generic_to_shared(sm);
    const unsigned sdst = sbase + (unsigned)(lr * SROW + lc) * 2;

    const __nv_bfloat16* gsrc0 = Ahi    + (rowbase + lr) * K + lc;
    const __nv_bfloat16* gsrc1 = Alo    + (rowbase + lr) * K + lc;
    const __nv_bfloat16* gsrc2 = g_bthi + (colbase + lr) * K + lc;
    const __nv_bfloat16* gsrc3 = g_btlo + (colbase + lr) * K + lc;

    float acc[2][8][4];
#pragma unroll
    for (int i = 0; i < 2; i++)
#pragma unroll
        for (int j = 0; j < 8; j++)
#pragma unroll
            for (int q = 0; q < 4; q++) acc[i][j][q] = 0.f;

    const int KT = K >> 4;

    cpasync16(sdst + 0 * TILE * 2, gsrc0);
    cpasync16(sdst + 1 * TILE * 2, gsrc1);
    cpasync16(sdst + 2 * TILE * 2, gsrc2);
    cpasync16(sdst + 3 * TILE * 2, gsrc3);
    asm volatile("cp.async.commit_group;");

    const int a_row = (lane & 15);
    const int a_kh  = (lane >> 4) * 8;
    const int b_n   = (lane & 7) + (lane >> 4) * 8;
    const int b_kh  = ((lane >> 3) & 1) * 8;

    for (int it = 0; it < KT; it++) {
        if (it + 1 < KT) {
            unsigned d = sdst + (unsigned)(((it + 1) & 1) * 4) * TILE * 2;
            int ko = (it + 1) * 16;
            cpasync16(d + 0 * TILE * 2, gsrc0 + ko);
            cpasync16(d + 1 * TILE * 2, gsrc1 + ko);
            cpasync16(d + 2 * TILE * 2, gsrc2 + ko);
            cpasync16(d + 3 * TILE * 2, gsrc3 + ko);
            asm volatile("cp.async.commit_group;");
            asm volatile("cp.async.wait_group 1;");
        } else {
            asm volatile("cp.async.wait_group 0;");
        }
        __syncthreads();

        const unsigned ub = sbase + (unsigned)((it & 1) * 4) * TILE * 2;
        const unsigned uAh = ub + 0 * TILE * 2;
        const unsigned uAl = ub + 1 * TILE * 2;
        const unsigned uBh = ub + 2 * TILE * 2;
        const unsigned uBl = ub + 3 * TILE * 2;

        unsigned fah[2][4], fal[2][4];
#pragma unroll
        for (int mt = 0; mt < 2; mt++) {
            int r0 = wm * 32 + mt * 16;
            unsigned addr = (unsigned)((r0 + a_row) * SROW + a_kh) * 2;
            ldsm4(fah[mt][0], fah[mt][1], fah[mt][2], fah[mt][3], uAh + addr);
            ldsm4(fal[mt][0], fal[mt][1], fal[mt][2], fal[mt][3], uAl + addr);
        }

#pragma unroll
        for (int np = 0; np < 4; np++) {
            int n0 = wn * 64 + np * 16;
            unsigned addr = (unsigned)((n0 + b_n) * SROW + b_kh) * 2;
            unsigned bh0, bh1, bh2, bh3, bl0, bl1, bl2, bl3;
            ldsm4(bh0, bh1, bh2, bh3, uBh + addr);
            ldsm4(bl0, bl1, bl2, bl3, uBl + addr);
#pragma unroll
            for (int mt = 0; mt < 2; mt++) {
                MMA16816(acc[mt][2 * np],     fah[mt][0], fah[mt][1], fah[mt][2], fah[mt][3], bh0, bh1);
                MMA16816(acc[mt][2 * np],     fal[mt][0], fal[mt][1], fal[mt][2], fal[mt][3], bh0, bh1);
                MMA16816(acc[mt][2 * np],     fah[mt][0], fah[mt][1], fah[mt][2], fah[mt][3], bl0, bl1);
                MMA16816(acc[mt][2 * np + 1], fah[mt][0], fah[mt][1], fah[mt][2], fah[mt][3], bh2, bh3);
                MMA16816(acc[mt][2 * np + 1], fal[mt][0], fal[mt][1], fal[mt][2], fal[mt][3], bh2, bh3);
                MMA16816(acc[mt][2 * np + 1], fah[mt][0], fah[mt][1], fah[mt][2], fah[mt][3], bl2, bl3);
            }
        }
        __syncthreads();
    }

    const int g = lane >> 2, t = lane & 3;
#pragma unroll
    for (int mt = 0; mt < 2; mt++) {
#pragma unroll
        for (int nt = 0; nt < 8; nt++) {
            size_t r = rowbase + wm * 32 + mt * 16 + g;
            size_t c = colbase + wn * 64 + nt * 8 + 2 * t;
            *(float2*)(C + r * ldc + c)       = make_float2(acc[mt][nt][0], acc[mt][nt][1]);
            *(float2*)(C + (r + 8) * ldc + c) = make_float2(acc[mt][nt][2], acc[mt][nt][3]);
        }
    }
}

// ---------------- aggregation + epilogue -----------------------------------
// y layout: [NPAD][2d] fp32, self = cols [0,d), neigh = cols [d,2d).
// x2 unroll with independent accumulators (MLP=2) + __ldcg gathers (skip L1).

__global__ void k_agg128_relu(const float* __restrict__ y, const float* __restrict__ bias,
                              __nv_bfloat16* __restrict__ ohi, __nv_bfloat16* __restrict__ olo)
{
    int w = (blockIdx.x * blockDim.x + threadIdx.x) >> 5;
    int lane = threadIdx.x & 31;
    if (w >= NN) return;
    int s0 = g_off[w], s1 = g_off[w + 1];
    const float4* y4 = (const float4*)y;       // row stride = 64 float4
    float4 a0 = make_float4(0.f, 0.f, 0.f, 0.f), a1 = a0;
    int e = s0;
    for (; e + 2 <= s1; e += 2) {
        int i0 = g_csr[e], i1 = g_csr[e + 1];
        float4 v0 = __ldcg(&y4[(size_t)i0 * 64 + 32 + lane]);
        float4 v1 = __ldcg(&y4[(size_t)i1 * 64 + 32 + lane]);
        a0.x += v0.x; a0.y += v0.y; a0.z += v0.z; a0.w += v0.w;
        a1.x += v1.x; a1.y += v1.y; a1.z += v1.z; a1.w += v1.w;
    }
    if (e < s1) {
        float4 v = __ldcg(&y4[(size_t)g_csr[e] * 64 + 32 + lane]);
        a0.x += v.x; a0.y += v.y; a0.z += v.z; a0.w += v.w;
    }
    float4 acc = make_float4(a0.x + a1.x, a0.y + a1.y, a0.z + a1.z, a0.w + a1.w);

    float inv = (s1 > s0) ? 1.f / (float)(s1 - s0) : 0.f;
    float4 sv = y4[(size_t)w * 64 + lane];
    float4 bb = ((const float4*)bias)[lane];
    float4 o;
    o.x = fmaxf(sv.x + acc.x * inv + bb.x, 0.f);
    o.y = fmaxf(sv.y + acc.y * inv + bb.y, 0.f);
    o.z = fmaxf(sv.z + acc.z * inv + bb.z, 0.f);
    o.w = fmaxf(sv.w + acc.w * inv + bb.w, 0.f);

    __nv_bfloat16 hx = __float2bfloat16(o.x), hy = __float2bfloat16(o.y);
    __nv_bfloat16 hz = __float2bfloat16(o.z), hw = __float2bfloat16(o.w);
    __nv_bfloat162 h01, h23, l01, l23;
    h01.x = hx; h01.y = hy; h23.x = hz; h23.y = hw;
    l01.x = __float2bfloat16(o.x - __bfloat162float(hx));
    l01.y = __float2bfloat16(o.y - __bfloat162float(hy));
    l23.x = __float2bfloat16(o.z - __bfloat162float(hz));
    l23.y = __float2bfloat16(o.w - __bfloat162float(hw));
    uint2 hp, lp;
    hp.x = *(unsigned*)&h01; hp.y = *(unsigned*)&h23;
    lp.x = *(unsigned*)&l01; lp.y = *(unsigned*)&l23;
    *(uint2*)(ohi + (size_t)w * 128 + lane * 4) = hp;
    *(uint2*)(olo + (size_t)w * 128 + lane * 4) = lp;
}

__global__ void k_agg64_relu(const float* __restrict__ y, const float* __restrict__ bias,
                             __nv_bfloat16* __restrict__ ohi, __nv_bfloat16* __restrict__ olo)
{
    int w = (blockIdx.x * blockDim.x + threadIdx.x) >> 5;
    int lane = threadIdx.x & 31;
    if (w >= NN) return;
    int s0 = g_off[w], s1 = g_off[w + 1];
    const float2* y2 = (const float2*)y;       // row stride = 64 float2
    float2 a0 = make_float2(0.f, 0.f), a1 = a0;
    int e = s0;
    for (; e + 2 <= s1; e += 2) {
        int i0 = g_csr[e], i1 = g_csr[e + 1];
        float2 v0 = __ldcg(&y2[(size_t)i0 * 64 + 32 + lane]);
        float2 v1 = __ldcg(&y2[(size_t)i1 * 64 + 32 + lane]);
        a0.x += v0.x; a0.y += v0.y;
        a1.x += v1.x; a1.y += v1.y;
    }
    if (e < s1) {
        float2 v = __ldcg(&y2[(size_t)g_csr[e] * 64 + 32 + lane]);
        a0.x += v.x; a0.y += v.y;
    }
    float2 acc = make_float2(a0.x + a1.x, a0.y + a1.y);

    float inv = (s1 > s0) ? 1.f / (float)(s1 - s0) : 0.f;
    float2 sv = y2[(size_t)w * 64 + lane];
    float2 bb = ((const float2*)bias)[lane];
    float ox = fmaxf(sv.x + acc.x * inv + bb.x, 0.f);
    float oy = fmaxf(sv.y + acc.y * inv + bb.y, 0.f);

    __nv_bfloat16 hx = __float2bfloat16(ox), hy = __float2bfloat16(oy);
    __nv_bfloat162 h01, l01;
    h01.x = hx; h01.y = hy;
    l01.x = __float2bfloat16(ox - __bfloat162float(hx));
    l01.y = __float2bfloat16(oy - __bfloat162float(hy));
    *(unsigned*)(ohi + (size_t)w * 64 + lane * 2) = *(unsigned*)&h01;
    *(unsigned*)(olo + (size_t)w * 64 + lane * 2) = *(unsigned*)&l01;
}

__global__ void k_agg64_softmax(const float* __restrict__ y, const float* __restrict__ bias,
                                float* __restrict__ out)
{
    int w = (blockIdx.x * blockDim.x + threadIdx.x) >> 5;
    int lane = threadIdx.x & 31;
    if (w >= NN) return;
    int s0 = g_off[w], s1 = g_off[w + 1];
    const float2* y2 = (const float2*)y;
    float2 a0 = make_float2(0.f, 0.f), a1 = a0;
    int e = s0;
    for (; e + 2 <= s1; e += 2) {
        int i0 = g_csr[e], i1 = g_csr[e + 1];
        float2 v0 = __ldcg(&y2[(size_t)i0 * 64 + 32 + lane]);
        float2 v1 = __ldcg(&y2[(size_t)i1 * 64 + 32 + lane]);
        a0.x += v0.x; a0.y += v0.y;
        a1.x += v1.x; a1.y += v1.y;
    }
    if (e < s1) {
        float2 v = __ldcg(&y2[(size_t)g_csr[e] * 64 + 32 + lane]);
        a0.x += v.x; a0.y += v.y;
    }
    float2 acc = make_float2(a0.x + a1.x, a0.y + a1.y);

    float inv = (s1 > s0) ? 1.f / (float)(s1 - s0) : 0.f;
    float2 sv = y2[(size_t)w * 64 + lane];
    float2 bb = ((const float2*)bias)[lane];
    float vx = sv.x + acc.x * inv + bb.x;
    float vy = sv.y + acc.y * inv + bb.y;

    float m = fmaxf(vx, vy);
#pragma unroll
    for (int o = 16; o > 0; o >>= 1)
        m = fmaxf(m, __shfl_xor_sync(0xffffffffu, m, o));
    float ex = __expf(vx - m);
    float ey = __expf(vy - m);
    float s = ex + ey;
#pragma unroll
    for (int o = 16; o > 0; o >>= 1)
        s += __shfl_xor_sync(0xffffffffu, s, o);
    float r = 1.f / s;
    ((float2*)out)[(size_t)w * 32 + lane] = make_float2(ex * r, ey * r);
}

// ---------------- launch ----------------------------------------------------
extern "C" void kernel_launch(void* const* d_in, const int* in_sizes, int n_in,
                              void* d_out, int out_size)
{
    const float* x   = (const float*)d_in[0];
    const int*   src = (const int*)d_in[1];
    const int*   dst = (const int*)d_in[2];
    const float* w1s = (const float*)d_in[3];
    const float* w1n = (const float*)d_in[4];
    const float* b1  = (const float*)d_in[5];
    const float* w2s = (const float*)d_in[6];
    const float* w2n = (const float*)d_in[7];
    const float* b2  = (const float*)d_in[8];
    const float* w3s = (const float*)d_in[9];
    const float* w3n = (const float*)d_in[10];
    const float* b3  = (const float*)d_in[11];
    float* out = (float*)d_out;
    int E = in_sizes[1];
    if (E > EMAX) E = EMAX;

    __nv_bfloat16 *p_ahi, *p_alo;
    float* p_y;
    cudaGetSymbolAddress((void**)&p_ahi, g_ahi);
    cudaGetSymbolAddress((void**)&p_alo, g_alo);
    cudaGetSymbolAddress((void**)&p_y, g_y);

    const int MB = NPAD / 128;                    // 782
    const int AGG_BLKS = (NN * 32 + 255) / 256;   // 12500
    const int E4 = (E + 3) / 4;

    // Layer 1 (GEMM at launch index 3 for the ncu window)
    k_split4<<<(NN * 128 / 4 + 255) / 256, 256>>>(x, NN * 128 / 4);
    k_pack<<<(2 * 128 * 128 + 255) / 256, 256>>>(w1s, w1n, 128, 128);
    k_zero_deg<<<256, 256>>>();
    k_gemm_mma<<<dim3(MB, 2), 256>>>(p_ahi, p_alo, p_y, 128, 256);
    k_count<<<(E4 + 255) / 256, 256>>>(dst, E);
    k_scan<<<1, 1024>>>();
    k_scatter<<<(E4 + 255) / 256, 256>>>(src, dst, E);
    k_agg128_relu<<<AGG_BLKS, 256>>>(p_y, b1, p_ahi, p_alo);

    // Layer 2: 128 -> 64 (2N = 128)
    k_pack<<<(2 * 64 * 128 + 255) / 256, 256>>>(w2s, w2n, 128, 64);
    k_gemm_mma<<<dim3(MB, 1), 256>>>(p_ahi, p_alo, p_y, 128, 128);
    k_agg64_relu<<<AGG_BLKS, 256>>>(p_y, b2, p_ahi, p_alo);

    // Layer 3: 64 -> 64 (2N = 128) + softmax
    k_pack<<<(2 * 64 * 64 + 255) / 256, 256>>>(w3s, w3n, 64, 64);
    k_gemm_mma<<<dim3(MB, 1), 256>>>(p_ahi, p_alo, p_y, 64, 128);
    k_agg64_softmax<<<AGG_BLKS, 256>>>(p_y, b3, out);
}

// round 15
// speedup vs baseline: 1.1214x; 1.0240x over previous
#include <cuda_runtime.h>
#include <cuda_bf16.h>
#include <cuda_fp16.h>

#define NN   100000
#define NPAD 100096            // 782 * 128
#define EMAX 1600000
#define SROW 24                // smem row stride (bf16 elems); 48B -> conflict-free ldmatrix

// ---------------- scratch (device globals; no allocation allowed) ----------
__device__ __nv_bfloat16 g_ahi[(size_t)NPAD * 128];
__device__ __nv_bfloat16 g_alo[(size_t)NPAD * 128];
__device__ float         g_ys[(size_t)NPAD * 128];    // self projection (fp32)
__device__ __half        g_yh[(size_t)NPAD * 128];    // neigh projection (fp16)
__device__ __nv_bfloat16 g_bthi[256 * 128];           // packed B^T hi  [2N][K]
__device__ __nv_bfloat16 g_btlo[256 * 128];           // packed B^T lo
__device__ int g_deg[NN];
__device__ int g_off[NN + 1];
__device__ int g_cur[NN];
__device__ int g_csr[EMAX];

// ---------------- CSR build -------------------------------------------------
__global__ void k_zero_deg() {
    for (int i = blockIdx.x * blockDim.x + threadIdx.x; i < NN;
         i += gridDim.x * blockDim.x)
        g_deg[i] = 0;
}

__global__ void k_count(const int* __restrict__ dst, int E) {
    int i0 = (blockIdx.x * blockDim.x + threadIdx.x) * 4;
    if (i0 + 3 < E) {
        int4 d = *(const int4*)(dst + i0);
        atomicAdd(&g_deg[d.x], 1);
        atomicAdd(&g_deg[d.y], 1);
        atomicAdd(&g_deg[d.z], 1);
        atomicAdd(&g_deg[d.w], 1);
    } else {
        for (int j = 0; j < 4; j++) {
            int i = i0 + j;
            if (i < E) atomicAdd(&g_deg[dst[i]], 1);
        }
    }
}

__global__ void k_scan() {
    __shared__ int ss[1024];
    int t = threadIdx.x;
    const int CH = (NN + 1023) / 1024;
    int beg = t * CH; if (beg > NN) beg = NN;
    int end = beg + CH; if (end > NN) end = NN;
    int s = 0;
    for (int i = beg; i < end; i++) s += g_deg[i];
    ss[t] = s;
    __syncthreads();
    for (int d = 1; d < 1024; d <<= 1) {
        int v = (t >= d) ? ss[t - d] : 0;
        __syncthreads();
        ss[t] += v;
        __syncthreads();
    }
    int run = ss[t] - s;
    for (int i = beg; i < end; i++) {
        g_off[i] = run;
        g_cur[i] = run;
        run += g_deg[i];
    }
    if (t == 1023) g_off[NN] = ss[1023];
}

__global__ void k_scatter(const int* __restrict__ src, const int* __restrict__ dst, int E) {
    int i0 = (blockIdx.x * blockDim.x + threadIdx.x) * 4;
    if (i0 + 3 < E) {
        int4 d = *(const int4*)(dst + i0);
        int4 s = *(const int4*)(src + i0);
        int p0 = atomicAdd(&g_cur[d.x], 1);
        int p1 = atomicAdd(&g_cur[d.y], 1);
        int p2 = atomicAdd(&g_cur[d.z], 1);
        int p3 = atomicAdd(&g_cur[d.w], 1);
        g_csr[p0] = s.x; g_csr[p1] = s.y; g_csr[p2] = s.z; g_csr[p3] = s.w;
    } else {
        for (int j = 0; j < 4; j++) {
            int i = i0 + j;
            if (i < E) {
                int p = atomicAdd(&g_cur[dst[i]], 1);
                g_csr[p] = src[i];
            }
        }
    }
}

// ---------------- weight pack: [Ws | Wn] -> B^T bf16 hi/lo -----------------
__global__ void k_pack(const float* __restrict__ ws, const float* __restrict__ wn,
                       int K, int N)
{
    int idx = blockIdx.x * blockDim.x + threadIdx.x;
    int total = 2 * N * K;
    if (idx >= total) return;
    int n = idx / K, k = idx - n * K;
    float v = (n < N) ? ws[k * N + n] : wn[k * N + (n - N)];
    __nv_bfloat16 h = __float2bfloat16(v);
    g_bthi[n * K + k] = h;
    g_btlo[n * K + k] = __float2bfloat16(v - __bfloat162float(h));
}

// ---------------- fp32 -> bf16 hi/lo split of the input features -----------
__global__ void k_split4(const float* __restrict__ x, int n4) {
    int i = blockIdx.x * blockDim.x + threadIdx.x;
    if (i >= n4) return;
    float4 v = ((const float4*)x)[i];
    __nv_bfloat16 hx = __float2bfloat16(v.x), hy = __float2bfloat16(v.y);
    __nv_bfloat16 hz = __float2bfloat16(v.z), hw = __float2bfloat16(v.w);
    __nv_bfloat162 h01, h23, l01, l23;
    h01.x = hx; h01.y = hy; h23.x = hz; h23.y = hw;
    l01.x = __float2bfloat16(v.x - __bfloat162float(hx));
    l01.y = __float2bfloat16(v.y - __bfloat162float(hy));
    l23.x = __float2bfloat16(v.z - __bfloat162float(hz));
    l23.y = __float2bfloat16(v.w - __bfloat162float(hw));
    uint2 hp, lp;
    hp.x = *(unsigned*)&h01; hp.y = *(unsigned*)&h23;
    lp.x = *(unsigned*)&l01; lp.y = *(unsigned*)&l23;
    ((uint2*)g_ahi)[i] = hp;
    ((uint2*)g_alo)[i] = lp;
}

// ---------------- tensor-core GEMM (split bf16, 3 products, pipelined) ------
// (EXACT R5 mainloop — empirically fastest; only the epilogue changed.)
#define MMA16816(d, a0, a1, a2, a3, b0, b1)                                    \
    asm volatile(                                                              \
        "mma.sync.aligned.m16n8k16.row.col.f32.bf16.bf16.f32 "                 \
        "{%0,%1,%2,%3}, {%4,%5,%6,%7}, {%8,%9}, {%0,%1,%2,%3};"               \
        : "+f"(d[0]), "+f"(d[1]), "+f"(d[2]), "+f"(d[3])                       \
        : "r"(a0), "r"(a1), "r"(a2), "r"(a3), "r"(b0), "r"(b1))

__device__ __forceinline__ void ldsm4(unsigned& r0, unsigned& r1,
                                      unsigned& r2, unsigned& r3, unsigned addr) {
    asm volatile("ldmatrix.sync.aligned.m8n8.x4.shared.b16 {%0,%1,%2,%3}, [%4];"
                 : "=r"(r0), "=r"(r1), "=r"(r2), "=r"(r3) : "r"(addr));
}

__device__ __forceinline__ void cpasync16(unsigned dst, const void* src) {
    asm volatile("cp.async.ca.shared.global [%0], [%1], 16;" :: "r"(dst), "l"(src));
}

// C = A[M,K] * Bt[2Nself,K]^T. Self cols -> Cs fp32 [M][Nself],
// neigh cols -> Ch fp16 [M][Nself]. Block tile 128x128, 8 warps (4m x 2n).
__global__ __launch_bounds__(256, 2)
void k_gemm_mma(const __nv_bfloat16* __restrict__ Ahi,
                const __nv_bfloat16* __restrict__ Alo,
                float* __restrict__ Cs, __half* __restrict__ Ch,
                int K, int Nself)
{
    __shared__ __align__(16) __nv_bfloat16 sm[2 * 4 * 128 * SROW];
    const int TILE = 128 * SROW;                // elems per tile

    const int tid = threadIdx.x;
    const int warp = tid >> 5, lane = tid & 31;
    const int wm = warp & 3, wn = warp >> 2;
    const size_t rowbase = (size_t)blockIdx.x * 128;
    const int    colbase = blockIdx.y * 128;

    const int lr = tid >> 1;
    const int lc = (tid & 1) * 8;

    const unsigned sbase = (unsigned)__cvta_generic_to_shared(sm);
    const unsigned sdst = sbase + (unsigned)(lr * SROW + lc) * 2;

    const __nv_bfloat16* gsrc0 = Ahi    + (rowbase + lr) * K + lc;
    const __nv_bfloat16* gsrc1 = Alo    + (rowbase + lr) * K + lc;
    const __nv_bfloat16* gsrc2 = g_bthi + (size_t)(colbase + lr) * K + lc;
    const __nv_bfloat16* gsrc3 = g_btlo + (size_t)(colbase + lr) * K + lc;

    float acc[2][8][4];
#pragma unroll
    for (int i = 0; i < 2; i++)
#pragma unroll
        for (int j = 0; j < 8; j++)
#pragma unroll
            for (int q = 0; q < 4; q++) acc[i][j][q] = 0.f;

    const int KT = K >> 4;

    cpasync16(sdst + 0 * TILE * 2, gsrc0);
    cpasync16(sdst + 1 * TILE * 2, gsrc1);
    cpasync16(sdst + 2 * TILE * 2, gsrc2);
    cpasync16(sdst + 3 * TILE * 2, gsrc3);
    asm volatile("cp.async.commit_group;");

    const int a_row = (lane & 15);
    const int a_kh  = (lane >> 4) * 8;
    const int b_n   = (lane & 7) + (lane >> 4) * 8;
    const int b_kh  = ((lane >> 3) & 1) * 8;

    for (int it = 0; it < KT; it++) {
        if (it + 1 < KT) {
            unsigned d = sdst + (unsigned)(((it + 1) & 1) * 4) * TILE * 2;
            int ko = (it + 1) * 16;
            cpasync16(d + 0 * TILE * 2, gsrc0 + ko);
            cpasync16(d + 1 * TILE * 2, gsrc1 + ko);
            cpasync16(d + 2 * TILE * 2, gsrc2 + ko);
            cpasync16(d + 3 * TILE * 2, gsrc3 + ko);
            asm volatile("cp.async.commit_group;");
            asm volatile("cp.async.wait_group 1;");
        } else {
            asm volatile("cp.async.wait_group 0;");
        }
        __syncthreads();

        const unsigned ub = sbase + (unsigned)((it & 1) * 4) * TILE * 2;
        const unsigned uAh = ub + 0 * TILE * 2;
        const unsigned uAl = ub + 1 * TILE * 2;
        const unsigned uBh = ub + 2 * TILE * 2;
        const unsigned uBl = ub + 3 * TILE * 2;

        unsigned fah[2][4], fal[2][4];
#pragma unroll
        for (int mt = 0; mt < 2; mt++) {
            int r0 = wm * 32 + mt * 16;
            unsigned addr = (unsigned)((r0 + a_row) * SROW + a_kh) * 2;
            ldsm4(fah[mt][0], fah[mt][1], fah[mt][2], fah[mt][3], uAh + addr);
            ldsm4(fal[mt][0], fal[mt][1], fal[mt][2], fal[mt][3], uAl + addr);
        }

#pragma unroll
        for (int np = 0; np < 4; np++) {
            int n0 = wn * 64 + np * 16;
            unsigned addr = (unsigned)((n0 + b_n) * SROW + b_kh) * 2;
            unsigned bh0, bh1, bh2, bh3, bl0, bl1, bl2, bl3;
            ldsm4(bh0, bh1, bh2, bh3, uBh + addr);
            ldsm4(bl0, bl1, bl2, bl3, uBl + addr);
#pragma unroll
            for (int mt = 0; mt < 2; mt++) {
                MMA16816(acc[mt][2 * np],     fah[mt][0], fah[mt][1], fah[mt][2], fah[mt][3], bh0, bh1);
                MMA16816(acc[mt][2 * np],     fal[mt][0], fal[mt][1], fal[mt][2], fal[mt][3], bh0, bh1);
                MMA16816(acc[mt][2 * np],     fah[mt][0], fah[mt][1], fah[mt][2], fah[mt][3], bl0, bl1);
                MMA16816(acc[mt][2 * np + 1], fah[mt][0], fah[mt][1], fah[mt][2], fah[mt][3], bh2, bh3);
                MMA16816(acc[mt][2 * np + 1], fal[mt][0], fal[mt][1], fal[mt][2], fal[mt][3], bh2, bh3);
                MMA16816(acc[mt][2 * np + 1], fah[mt][0], fah[mt][1], fah[mt][2], fah[mt][3], bl2, bl3);
            }
        }
        __syncthreads();
    }

    // epilogue: warp's 64-col span is entirely self (fp32) or entirely neigh (fp16)
    const int cg = colbase + wn * 64;
    const int g = lane >> 2, t = lane & 3;
    if (cg < Nself) {
#pragma unroll
        for (int mt = 0; mt < 2; mt++) {
#pragma unroll
            for (int nt = 0; nt < 8; nt++) {
                size_t r = rowbase + wm * 32 + mt * 16 + g;
                int c = cg + nt * 8 + 2 * t;
                *(float2*)(Cs + r * Nself + c)       = make_float2(acc[mt][nt][0], acc[mt][nt][1]);
                *(float2*)(Cs + (r + 8) * Nself + c) = make_float2(acc[mt][nt][2], acc[mt][nt][3]);
            }
        }
    } else {
        const int c0 = cg - Nself;
#pragma unroll
        for (int mt = 0; mt < 2; mt++) {
#pragma unroll
            for (int nt = 0; nt < 8; nt++) {
                size_t r = rowbase + wm * 32 + mt * 16 + g;
                int c = c0 + nt * 8 + 2 * t;
                *(__half2*)(Ch + r * Nself + c) =
                    __float22half2_rn(make_float2(acc[mt][nt][0], acc[mt][nt][1]));
                *(__half2*)(Ch + (r + 8) * Nself + c) =
                    __float22half2_rn(make_float2(acc[mt][nt][2], acc[mt][nt][3]));
            }
        }
    }
}

// ---------------- aggregation + epilogue -----------------------------------
// ys: fp32 [N][d] (self, streamed). yh: fp16 [N][d] (neigh, gathered).
// fp32 accumulation; x2 unroll; __ldcg gathers.

__global__ void k_agg128_relu(const float* __restrict__ ys, const __half* __restrict__ yh,
                              const float* __restrict__ bias,
                              __nv_bfloat16* __restrict__ ohi, __nv_bfloat16* __restrict__ olo)
{
    int w = (blockIdx.x * blockDim.x + threadIdx.x) >> 5;
    int lane = threadIdx.x & 31;
    if (w >= NN) return;
    int s0 = g_off[w], s1 = g_off[w + 1];
    const uint2* yh2 = (const uint2*)yh;       // row = 32 uint2 (4 halfs each)
    float4 a0 = make_float4(0.f, 0.f, 0.f, 0.f), a1 = a0;
    int e = s0;
    for (; e + 2 <= s1; e += 2) {
        int i0 = g_csr[e], i1 = g_csr[e + 1];
        uint2 u0 = __ldcg(&yh2[(size_t)i0 * 32 + lane]);
        uint2 u1 = __ldcg(&yh2[(size_t)i1 * 32 + lane]);
        float2 f00 = __half22float2(*(__half2*)&u0.x);
        float2 f01 = __half22float2(*(__half2*)&u0.y);
        float2 f10 = __half22float2(*(__half2*)&u1.x);
        float2 f11 = __half22float2(*(__half2*)&u1.y);
        a0.x += f00.x; a0.y += f00.y; a0.z += f01.x; a0.w += f01.y;
        a1.x += f10.x; a1.y += f10.y; a1.z += f11.x; a1.w += f11.y;
    }
    if (e < s1) {
        uint2 u = __ldcg(&yh2[(size_t)g_csr[e] * 32 + lane]);
        float2 f0 = __half22float2(*(__half2*)&u.x);
        float2 f1 = __half22float2(*(__half2*)&u.y);
        a0.x += f0.x; a0.y += f0.y; a0.z += f1.x; a0.w += f1.y;
    }
    float4 acc = make_float4(a0.x + a1.x, a0.y + a1.y, a0.z + a1.z, a0.w + a1.w);

    float inv = (s1 > s0) ? 1.f / (float)(s1 - s0) : 0.f;
    float4 sv = ((const float4*)ys)[(size_t)w * 32 + lane];
    float4 bb = ((const float4*)bias)[lane];
    float4 o;
    o.x = fmaxf(sv.x + acc.x * inv + bb.x, 0.f);
    o.y = fmaxf(sv.y + acc.y * inv + bb.y, 0.f);
    o.z = fmaxf(sv.z + acc.z * inv + bb.z, 0.f);
    o.w = fmaxf(sv.w + acc.w * inv + bb.w, 0.f);

    __nv_bfloat16 hx = __float2bfloat16(o.x), hy = __float2bfloat16(o.y);
    __nv_bfloat16 hz = __float2bfloat16(o.z), hw = __float2bfloat16(o.w);
    __nv_bfloat162 h01, h23, l01, l23;
    h01.x = hx; h01.y = hy; h23.x = hz; h23.y = hw;
    l01.x = __float2bfloat16(o.x - __bfloat162float(hx));
    l01.y = __float2bfloat16(o.y - __bfloat162float(hy));
    l23.x = __float2bfloat16(o.z - __bfloat162float(hz));
    l23.y = __float2bfloat16(o.w - __bfloat162float(hw));
    uint2 hp, lp;
    hp.x = *(unsigned*)&h01; hp.y = *(unsigned*)&h23;
    lp.x = *(unsigned*)&l01; lp.y = *(unsigned*)&l23;
    *(uint2*)(ohi + (size_t)w * 128 + lane * 4) = hp;
    *(uint2*)(olo + (size_t)w * 128 + lane * 4) = lp;
}

__global__ void k_agg64_relu(const float* __restrict__ ys, const __half* __restrict__ yh,
                             const float* __restrict__ bias,
                             __nv_bfloat16* __restrict__ ohi, __nv_bfloat16* __restrict__ olo)
{
    int w = (blockIdx.x * blockDim.x + threadIdx.x) >> 5;
    int lane = threadIdx.x & 31;
    if (w >= NN) return;
    int s0 = g_off[w], s1 = g_off[w + 1];
    const __half2* yh2 = (const __half2*)yh;   // row = 32 half2
    float2 a0 = make_float2(0.f, 0.f), a1 = a0;
    int e = s0;
    for (; e + 2 <= s1; e += 2) {
        int i0 = g_csr[e], i1 = g_csr[e + 1];
        __half2 u0 = __ldcg(&yh2[(size_t)i0 * 32 + lane]);
        __half2 u1 = __ldcg(&yh2[(size_t)i1 * 32 + lane]);
        float2 f0 = __half22float2(u0);
        float2 f1 = __half22float2(u1);
        a0.x += f0.x; a0.y += f0.y;
        a1.x += f1.x; a1.y += f1.y;
    }
    if (e < s1) {
        float2 f = __half22float2(__ldcg(&yh2[(size_t)g_csr[e] * 32 + lane]));
        a0.x += f.x; a0.y += f.y;
    }
    float2 acc = make_float2(a0.x + a1.x, a0.y + a1.y);

    float inv = (s1 > s0) ? 1.f / (float)(s1 - s0) : 0.f;
    float2 sv = ((const float2*)ys)[(size_t)w * 32 + lane];
    float2 bb = ((const float2*)bias)[lane];
    float ox = fmaxf(sv.x + acc.x * inv + bb.x, 0.f);
    float oy = fmaxf(sv.y + acc.y * inv + bb.y, 0.f);

    __nv_bfloat16 hx = __float2bfloat16(ox), hy = __float2bfloat16(oy);
    __nv_bfloat162 h01, l01;
    h01.x = hx; h01.y = hy;
    l01.x = __float2bfloat16(ox - __bfloat162float(hx));
    l01.y = __float2bfloat16(oy - __bfloat162float(hy));
    *(unsigned*)(ohi + (size_t)w * 64 + lane * 2) = *(unsigned*)&h01;
    *(unsigned*)(olo + (size_t)w * 64 + lane * 2) = *(unsigned*)&l01;
}

__global__ void k_agg64_softmax(const float* __restrict__ ys, const __half* __restrict__ yh,
                                const float* __restrict__ bias, float* __restrict__ out)
{
    int w = (blockIdx.x * blockDim.x + threadIdx.x) >> 5;
    int lane = threadIdx.x & 31;
    if (w >= NN) return;
    int s0 = g_off[w], s1 = g_off[w + 1];
    const __half2* yh2 = (const __half2*)yh;
    float2 a0 = make_float2(0.f, 0.f), a1 = a0;
    int e = s0;
    for (; e + 2 <= s1; e += 2) {
        int i0 = g_csr[e], i1 = g_csr[e + 1];
        __half2 u0 = __ldcg(&yh2[(size_t)i0 * 32 + lane]);
        __half2 u1 = __ldcg(&yh2[(size_t)i1 * 32 + lane]);
        float2 f0 = __half22float2(u0);
        float2 f1 = __half22float2(u1);
        a0.x += f0.x; a0.y += f0.y;
        a1.x += f1.x; a1.y += f1.y;
    }
    if (e < s1) {
        float2 f = __half22float2(__ldcg(&yh2[(size_t)g_csr[e] * 32 + lane]));
        a0.x += f.x; a0.y += f.y;
    }
    float2 acc = make_float2(a0.x + a1.x, a0.y + a1.y);

    float inv = (s1 > s0) ? 1.f / (float)(s1 - s0) : 0.f;
    float2 sv = ((const float2*)ys)[(size_t)w * 32 + lane];
    float2 bb = ((const float2*)bias)[lane];
    float vx = sv.x + acc.x * inv + bb.x;
    float vy = sv.y + acc.y * inv + bb.y;

    float m = fmaxf(vx, vy);
#pragma unroll
    for (int o = 16; o > 0; o >>= 1)
        m = fmaxf(m, __shfl_xor_sync(0xffffffffu, m, o));
    float ex = __expf(vx - m);
    float ey = __expf(vy - m);
    float s = ex + ey;
#pragma unroll
    for (int o = 16; o > 0; o >>= 1)
        s += __shfl_xor_sync(0xffffffffu, s, o);
    float r = 1.f / s;
    ((float2*)out)[(size_t)w * 32 + lane] = make_float2(ex * r, ey * r);
}

// ---------------- launch ----------------------------------------------------
extern "C" void kernel_launch(void* const* d_in, const int* in_sizes, int n_in,
                              void* d_out, int out_size)
{
    const float* x   = (const float*)d_in[0];
    const int*   src = (const int*)d_in[1];
    const int*   dst = (const int*)d_in[2];
    const float* w1s = (const float*)d_in[3];
    const float* w1n = (const float*)d_in[4];
    const float* b1  = (const float*)d_in[5];
    const float* w2s = (const float*)d_in[6];
    const float* w2n = (const float*)d_in[7];
    const float* b2  = (const float*)d_in[8];
    const float* w3s = (const float*)d_in[9];
    const float* w3n = (const float*)d_in[10];
    const float* b3  = (const float*)d_in[11];
    float* out = (float*)d_out;
    int E = in_sizes[1];
    if (E > EMAX) E = EMAX;

    __nv_bfloat16 *p_ahi, *p_alo;
    float* p_ys;
    __half* p_yh;
    cudaGetSymbolAddress((void**)&p_ahi, g_ahi);
    cudaGetSymbolAddress((void**)&p_alo, g_alo);
    cudaGetSymbolAddress((void**)&p_ys, g_ys);
    cudaGetSymbolAddress((void**)&p_yh, g_yh);

    const int MB = NPAD / 128;                    // 782
    const int AGG_BLKS = (NN * 32 + 255) / 256;   // 12500
    const int E4 = (E + 3) / 4;

    // Layer 1 (GEMM at launch index 3 for the ncu window)
    k_split4<<<(NN * 128 / 4 + 255) / 256, 256>>>(x, NN * 128 / 4);
    k_pack<<<(2 * 128 * 128 + 255) / 256, 256>>>(w1s, w1n, 128, 128);
    k_zero_deg<<<256, 256>>>();
    k_gemm_mma<<<dim3(MB, 2), 256>>>(p_ahi, p_alo, p_ys, p_yh, 128, 128);
    k_count<<<(E4 + 255) / 256, 256>>>(dst, E);
    k_scan<<<1, 1024>>>();
    k_scatter<<<(E4 + 255) / 256, 256>>>(src, dst, E);
    k_agg128_relu<<<AGG_BLKS, 256>>>(p_ys, p_yh, b1, p_ahi, p_alo);

    // Layer 2: 128 -> 64 (2N = 128)
    k_pack<<<(2 * 64 * 128 + 255) / 256, 256>>>(w2s, w2n, 128, 64);
    k_gemm_mma<<<dim3(MB, 1), 256>>>(p_ahi, p_alo, p_ys, p_yh, 128, 64);
    k_agg64_relu<<<AGG_BLKS, 256>>>(p_ys, p_yh, b2, p_ahi, p_alo);

    // Layer 3: 64 -> 64 (2N = 128) + softmax
    k_pack<<<(2 * 64 * 64 + 255) / 256, 256>>>(w3s, w3n, 64, 64);
    k_gemm_mma<<<dim3(MB, 1), 256>>>(p_ahi, p_alo, p_ys, p_yh, 64, 64);
    k_agg64_softmax<<<AGG_BLKS, 256>>>(p_ys, p_yh, b3, out);
}